// round 3
// baseline (speedup 1.0000x reference)
#include <cuda_runtime.h>

// x: (32,3,16,32,32) fp32; weight: (3,16,3,3,3); bias scalar; out: (32,1,31,63,63)
// ConvTranspose3d s=2 p=1 k=3: per dim even o -> tap k=1 (i=o/2);
// odd o -> k=0 (i=(o+1)/2), k=2 (i=(o-1)/2). All indices in-range for these shapes.

#define DIN 16
#define HIN 32
#define WIN 32
#define XCH (DIN*HIN*WIN)   // 16384
#define XB  (3*XCH)         // 49152
#define GSTRIDE 20          // floats per (ocpair,kd,kh) group: 18 used + 2 pad (80B)
#define WSH (8*9*GSTRIDE)   // 1440 floats

__device__ __forceinline__ unsigned long long dup2(float x) {
    unsigned long long r;
    asm("mov.b64 %0, {%1, %1};" : "=l"(r) : "f"(x));
    return r;
}
__device__ __forceinline__ void ffma2(unsigned long long &d, double w, unsigned long long x) {
    asm("fma.rn.f32x2 %0, %1, %2, %0;"
        : "+l"(d) : "l"(__double_as_longlong(w)), "l"(x));
}
__device__ __forceinline__ float2 unpk(unsigned long long v) {
    float lo, hi;
    asm("mov.b64 {%0, %1}, %2;" : "=f"(lo), "=f"(hi) : "l"(v));
    return make_float2(lo, hi);
}

// One warp = one output row (b,od,oh). Lane c -> ow=2c (even) and 2c+1 (odd, masked c==31).
// Weight pack: sw[((ocp*3+kd)*3+kh)*20 + 2*s + half], s = ic*3+kw, half = oc within pair.
template<int ND, int NH>
__device__ __forceinline__ void run_row(
    const float* __restrict__ xb, const float* __restrict__ sw,
    float* __restrict__ op, int id0, int id1, int ih0, int ih1, int c, float bv)
{
    float xv[ND][NH][3][2];
    int cp1 = (c < 31) ? c + 1 : 31;   // lane31 odd result masked at store
    #pragma unroll
    for (int a = 0; a < ND; a++) {
        int idv = (a == 0) ? id0 : id1;
        #pragma unroll
        for (int h = 0; h < NH; h++) {
            int ihv = (h == 0) ? ih0 : ih1;
            const float* p = xb + idv * (HIN * WIN) + ihv * WIN;
            #pragma unroll
            for (int ic = 0; ic < 3; ic++) {
                xv[a][h][ic][0] = __ldg(p + ic * XCH + c);
                xv[a][h][ic][1] = __ldg(p + ic * XCH + cp1);
            }
        }
    }

    unsigned long long V0[8], V1[8];   // packed (oc0,oc1) accumulators, even/odd output
    #pragma unroll
    for (int i = 0; i < 8; i++) { V0[i] = 0ull; V1[i] = 0ull; }

    #pragma unroll
    for (int a = 0; a < ND; a++) {
        const int KD = (ND == 1) ? 1 : a * 2;
        #pragma unroll
        for (int h = 0; h < NH; h++) {
            const int KH = (NH == 1) ? 1 : h * 2;
            unsigned long long x00 = dup2(xv[a][h][0][0]);
            unsigned long long x01 = dup2(xv[a][h][0][1]);
            unsigned long long x10 = dup2(xv[a][h][1][0]);
            unsigned long long x11 = dup2(xv[a][h][1][1]);
            unsigned long long x20 = dup2(xv[a][h][2][0]);
            unsigned long long x21 = dup2(xv[a][h][2][1]);
            #pragma unroll
            for (int ocp = 0; ocp < 8; ocp++) {
                const float* g = sw + ((ocp * 3 + KD) * 3 + KH) * GSTRIDE;
                double2 q01 = *(const double2*)(g);        // pairs s0,s1
                double2 q23 = *(const double2*)(g + 4);    // pairs s2,s3
                double2 q45 = *(const double2*)(g + 8);    // pairs s4,s5
                double2 q67 = *(const double2*)(g + 12);   // pairs s6,s7
                double  q8  = *(const double*)(g + 16);    // pair  s8
                // even output: kw=1 -> slots 1,4,7 at iw=c
                ffma2(V0[ocp], q01.y, x00);
                ffma2(V0[ocp], q45.x, x10);
                ffma2(V0[ocp], q67.y, x20);
                // odd output: kw=0 at iw=c+1 (slots 0,3,6), kw=2 at iw=c (slots 2,5,8)
                ffma2(V1[ocp], q01.x, x01);
                ffma2(V1[ocp], q23.x, x00);
                ffma2(V1[ocp], q23.y, x11);
                ffma2(V1[ocp], q45.y, x10);
                ffma2(V1[ocp], q67.x, x21);
                ffma2(V1[ocp], q8,    x20);
            }
        }
    }

    // streaming logsumexp (conv values bounded ~|5| here; fp32 exp safe at 1e-3 tol)
    float s0 = 0.f, s1 = 0.f;
    #pragma unroll
    for (int i = 0; i < 8; i++) {
        float2 e = unpk(V0[i]);
        s0 += __expf(e.x) + __expf(e.y);
        float2 o = unpk(V1[i]);
        s1 += __expf(o.x) + __expf(o.y);
    }
    float l0 = __logf(s0), l1 = __logf(s1);
    float h0 = __fdividef(l0, 6.f * (1.f + __expf(-(l0 + 3.f))));
    float h1 = __fdividef(l1, 6.f * (1.f + __expf(-(l1 + 3.f))));
    op[2 * c] = fminf(fmaxf(h0 - bv, -1.f), 1.f);
    if (c < 31) op[2 * c + 1] = fminf(fmaxf(h1 - bv, -1.f), 1.f);
}

__global__ __launch_bounds__(256)
void fused_convT_lse_hs_v3(
    const float* __restrict__ x,
    const float* __restrict__ w,
    const float* __restrict__ bias,
    float* __restrict__ out)
{
    __shared__ __align__(16) float sw[WSH];
    // src w[ic*432 + oc*27 + kd*9 + kh*3 + kw] -> paired pack
    for (int i = threadIdx.x; i < 1296; i += 256) {
        int half = i & 1, pi = i >> 1;
        int s = pi % 9, t = pi / 9;
        int kh = t % 3, t2 = t / 3;
        int kd = t2 % 3, ocp = t2 / 3;
        int oc = 2 * ocp + half;
        int ic = s / 3, kw = s - 3 * (s / 3);
        sw[((ocp * 3 + kd) * 3 + kh) * GSTRIDE + 2 * s + half] =
            w[ic * 432 + oc * 27 + kd * 9 + kh * 3 + kw];
    }
    __syncthreads();

    int warp = threadIdx.x >> 5, lane = threadIdx.x & 31;
    int gid = blockIdx.x * 8 + warp;   // row id in class-concatenated order

    // Rows regrouped by (od parity, oh parity) so a block's 8 warps share one class.
    // Class sizes (all divisible by 8): 16384 / 15872 / 15360 / 14880; total 62496.
    int cls, r;
    if (gid < 16384)      { cls = 0; r = gid; }
    else if (gid < 32256) { cls = 1; r = gid - 16384; }
    else if (gid < 47616) { cls = 2; r = gid - 32256; }
    else                  { cls = 3; r = gid - 47616; }

    int pd = cls >> 1, ph = cls & 1;
    int nhc = ph ? 31 : 32;
    int per_b = (pd ? 15 : 16) * nhc;
    int b = r / per_b; int rem = r - b * per_b;
    int idd = rem / nhc; int ihh = rem - idd * nhc;
    int od = 2 * idd + pd, oh = 2 * ihh + ph;

    const float* xb = x + (size_t)b * XB;
    float* op = out + ((size_t)(b * 31 + od) * 63 + oh) * 63;
    float bv = __ldg(bias);

    int id0, id1 = 0, ih0, ih1 = 0;
    if (pd) { id0 = (od + 1) >> 1; id1 = (od - 1) >> 1; } else id0 = od >> 1;
    if (ph) { ih0 = (oh + 1) >> 1; ih1 = (oh - 1) >> 1; } else ih0 = oh >> 1;

    if (cls == 0)      run_row<1, 1>(xb, sw, op, id0, id1, ih0, ih1, lane, bv);
    else if (cls == 1) run_row<1, 2>(xb, sw, op, id0, id1, ih0, ih1, lane, bv);
    else if (cls == 2) run_row<2, 1>(xb, sw, op, id0, id1, ih0, ih1, lane, bv);
    else               run_row<2, 2>(xb, sw, op, id0, id1, ih0, ih1, lane, bv);
}

extern "C" void kernel_launch(void* const* d_in, const int* in_sizes, int n_in,
                              void* d_out, int out_size)
{
    const float* x    = (const float*)d_in[0];
    const float* w    = (const float*)d_in[1];
    const float* bias = (const float*)d_in[2];
    float* out        = (float*)d_out;
    // rows = 32*31*63 = 62496, 8 warps/block -> 7812 blocks
    fused_convT_lse_hs_v3<<<7812, 256>>>(x, w, bias, out);
}

// round 4
// speedup vs baseline: 1.0530x; 1.0530x over previous
#include <cuda_runtime.h>

// x: (32,3,16,32,32) fp32; weight: (3,16,3,3,3); bias scalar; out: (32,1,31,63,63)
// ConvTranspose3d s=2 p=1 k=3: per dim even o -> tap k=1 (i=o/2);
// odd o -> k=0 (i=(o+1)/2), k=2 (i=(o-1)/2). All indices in-range for these shapes.

#define DIN 16
#define HIN 32
#define WIN 32
#define XCH (DIN*HIN*WIN)   // 16384
#define XB  (3*XCH)         // 49152
#define WSH (16*3*3*12)     // 1728 floats: sw[oc][kd][kh][slot], slot=ic*3+kw, pad 12

// One warp = one output row (b,od,oh). Lane c -> ow=2c (even) and 2c+1 (odd; lane31 masked).
template<int ND, int NH>
__device__ __forceinline__ void run_row(
    const float* __restrict__ xb, const float* __restrict__ sw,
    float* __restrict__ op, int id0, int id1, int ih0, int ih1, int c, float bv)
{
    float xv[ND][NH][3][2];
    int cp1 = (c < 31) ? c + 1 : 31;   // lane31's odd result masked at store
    #pragma unroll
    for (int a = 0; a < ND; a++) {
        int idv = (a == 0) ? id0 : id1;
        #pragma unroll
        for (int h = 0; h < NH; h++) {
            int ihv = (h == 0) ? ih0 : ih1;
            const float* p = xb + idv * (HIN * WIN) + ihv * WIN;
            #pragma unroll
            for (int ic = 0; ic < 3; ic++) {
                xv[a][h][ic][0] = __ldg(p + ic * XCH + c);
                xv[a][h][ic][1] = __ldg(p + ic * XCH + cp1);
            }
        }
    }

    // Streaming logsumexp: only 2 live accumulators (s0,s1).
    // Conv values bounded (~|5|) for this data; fp32 exp safe at 1e-3 tol.
    float s0 = 0.f, s1 = 0.f;
    #pragma unroll
    for (int oc = 0; oc < 16; oc++) {     // FULL unroll -> immediate LDS offsets
        float v0 = 0.f, v1 = 0.f;
        #pragma unroll
        for (int a = 0; a < ND; a++) {
            const int KD = (ND == 1) ? 1 : a * 2;
            #pragma unroll
            for (int h = 0; h < NH; h++) {
                const int KH = (NH == 1) ? 1 : h * 2;
                const float* g = sw + ((oc * 3 + KD) * 3 + KH) * 12;
                float4 A = *(const float4*)g;        // slots 0..3 (broadcast LDS.128)
                float4 B = *(const float4*)(g + 4);  // slots 4..7
                float  C = g[8];                     // slot 8
                float x00 = xv[a][h][0][0], x01 = xv[a][h][0][1];
                float x10 = xv[a][h][1][0], x11 = xv[a][h][1][1];
                float x20 = xv[a][h][2][0], x21 = xv[a][h][2][1];
                // even output (ow=2c): kw=1 -> slots 1,4,7 at iw=c
                v0 = fmaf(A.y, x00, v0);
                v0 = fmaf(B.x, x10, v0);
                v0 = fmaf(B.w, x20, v0);
                // odd output (ow=2c+1): kw=0 at iw=c+1 (slots 0,3,6), kw=2 at iw=c (2,5,8)
                v1 = fmaf(A.x, x01, v1);
                v1 = fmaf(A.z, x00, v1);
                v1 = fmaf(A.w, x11, v1);
                v1 = fmaf(B.y, x10, v1);
                v1 = fmaf(B.z, x21, v1);
                v1 = fmaf(C,   x20, v1);
            }
        }
        s0 += __expf(v0);
        s1 += __expf(v1);
    }

    float l0 = __logf(s0), l1 = __logf(s1);
    // hs = l * sigmoid(l+3)/6 = l / (6*(1+e^{-(l+3)}))
    float h0 = __fdividef(l0, 6.f * (1.f + __expf(-(l0 + 3.f))));
    float h1 = __fdividef(l1, 6.f * (1.f + __expf(-(l1 + 3.f))));
    op[2 * c] = fminf(fmaxf(h0 - bv, -1.f), 1.f);
    if (c < 31) op[2 * c + 1] = fminf(fmaxf(h1 - bv, -1.f), 1.f);
}

__global__ __launch_bounds__(256)
void fused_convT_lse_hs_v4(
    const float* __restrict__ x,
    const float* __restrict__ w,
    const float* __restrict__ bias,
    float* __restrict__ out)
{
    __shared__ __align__(16) float sw[WSH];
    // src w[ic*432 + oc*27 + kd*9 + kh*3 + kw]
    for (int i = threadIdx.x; i < 1296; i += 256) {
        int ic = i / 432;  int r = i - ic * 432;
        int oc = r / 27;   int tap = r - oc * 27;
        int kd = tap / 9;  int t2 = tap - kd * 9;
        int kh = t2 / 3;   int kw = t2 - kh * 3;
        sw[((oc * 3 + kd) * 3 + kh) * 12 + ic * 3 + kw] = w[i];
    }
    __syncthreads();

    int warp = threadIdx.x >> 5, lane = threadIdx.x & 31;
    int gid = blockIdx.x * 8 + warp;   // row id in class-concatenated order

    // Rows grouped by (od parity, oh parity): a block's 8 warps share one class
    // -> one straight-line specialized path per block (I$ locality, zero divergence).
    // Class sizes: 16384 / 15872 / 15360 / 14880 (all %8==0), total 62496.
    int cls, r;
    if (gid < 16384)      { cls = 0; r = gid; }
    else if (gid < 32256) { cls = 1; r = gid - 16384; }
    else if (gid < 47616) { cls = 2; r = gid - 32256; }
    else                  { cls = 3; r = gid - 47616; }

    int pd = cls >> 1, ph = cls & 1;
    int nhc = ph ? 31 : 32;
    int per_b = (pd ? 15 : 16) * nhc;
    int b = r / per_b; int rem = r - b * per_b;
    int idd = rem / nhc; int ihh = rem - idd * nhc;
    int od = 2 * idd + pd, oh = 2 * ihh + ph;

    const float* xb = x + (size_t)b * XB;
    float* op = out + ((size_t)(b * 31 + od) * 63 + oh) * 63;
    float bv = __ldg(bias);

    int id0, id1 = 0, ih0, ih1 = 0;
    if (pd) { id0 = (od + 1) >> 1; id1 = (od - 1) >> 1; } else id0 = od >> 1;
    if (ph) { ih0 = (oh + 1) >> 1; ih1 = (oh - 1) >> 1; } else ih0 = oh >> 1;

    if (cls == 0)      run_row<1, 1>(xb, sw, op, id0, id1, ih0, ih1, lane, bv);
    else if (cls == 1) run_row<1, 2>(xb, sw, op, id0, id1, ih0, ih1, lane, bv);
    else if (cls == 2) run_row<2, 1>(xb, sw, op, id0, id1, ih0, ih1, lane, bv);
    else               run_row<2, 2>(xb, sw, op, id0, id1, ih0, ih1, lane, bv);
}

extern "C" void kernel_launch(void* const* d_in, const int* in_sizes, int n_in,
                              void* d_out, int out_size)
{
    const float* x    = (const float*)d_in[0];
    const float* w    = (const float*)d_in[1];
    const float* bias = (const float*)d_in[2];
    float* out        = (float*)d_out;
    // rows = 32*31*63 = 62496, 8 warps/block -> 7812 blocks
    fused_convT_lse_hs_v4<<<7812, 256>>>(x, w, bias, out);
}

// round 5
// speedup vs baseline: 1.3320x; 1.2650x over previous
#include <cuda_runtime.h>

// x: (32,3,16,32,32) fp32; weight: (3,16,3,3,3); bias scalar; out: (32,1,31,63,63)
// ConvTranspose3d s=2 p=1 k=3: per dim even o -> tap k=1 (i=o/2);
// odd o -> k=0 (i=(o+1)/2), k=2 (i=(o-1)/2). All indices in-range for these shapes.

#define DIN 16
#define HIN 32
#define WIN 32
#define XCH (DIN*HIN*WIN)   // 16384
#define XB  (3*XCH)         // 49152
#define WSH (16*3*3*12)     // sw[oc][kd][kh][slot], slot=ic*3+kw (9 used, pad 12)

// Each thread: 4 consecutive outputs ow = 4c..4c+3 of one row (c = lane&15).
//   ow=4c   (even): kw=1 @ iw=2c
//   ow=4c+1 (odd):  kw=0 @ iw=2c+1, kw=2 @ iw=2c
//   ow=4c+2 (even): kw=1 @ iw=2c+1
//   ow=4c+3 (odd):  kw=0 @ iw=2c+2, kw=2 @ iw=2c+1   (c==15: ow=63 masked)
// x cache per (dtap,htap): 3 ic x 3 iw values; weights: one 9-float group per (oc,kd,kh)
// feeds 18 FMAs (was 9) -> LDS per output halves.
template<int ND, int NH>
__device__ __forceinline__ void run_quad(
    const float* __restrict__ xb, const float* __restrict__ sw,
    float* __restrict__ op, int id0, int id1, int ih0, int ih1, int c, float bv)
{
    float xv[ND][NH][3][3];
    int iw0 = 2 * c;
    int iw2 = (c < 15) ? iw0 + 2 : 31;   // clamp; value only used by masked ow=63
    #pragma unroll
    for (int a = 0; a < ND; a++) {
        int idv = (a == 0) ? id0 : id1;
        #pragma unroll
        for (int h = 0; h < NH; h++) {
            int ihv = (h == 0) ? ih0 : ih1;
            const float* p = xb + idv * (HIN * WIN) + ihv * WIN;
            #pragma unroll
            for (int ic = 0; ic < 3; ic++) {
                const float* q = p + ic * XCH;
                float2 t = __ldg((const float2*)(q + iw0));  // iw0 even -> 8B aligned
                xv[a][h][ic][0] = t.x;
                xv[a][h][ic][1] = t.y;
                xv[a][h][ic][2] = __ldg(q + iw2);
            }
        }
    }

    // Streaming logsumexp over oc (conv values bounded ~|5|; fp32 exp safe @1e-3 tol)
    float s0 = 0.f, s1 = 0.f, s2 = 0.f, s3 = 0.f;
    #pragma unroll
    for (int oc = 0; oc < 16; oc++) {
        float v0 = 0.f, v1 = 0.f, v2 = 0.f, v3 = 0.f;
        #pragma unroll
        for (int a = 0; a < ND; a++) {
            const int KD = (ND == 1) ? 1 : a * 2;
            #pragma unroll
            for (int h = 0; h < NH; h++) {
                const int KH = (NH == 1) ? 1 : h * 2;
                const float* g = sw + ((oc * 3 + KD) * 3 + KH) * 12;
                float4 A = *(const float4*)g;        // slots 0..3 (kw0:0,3,6 kw1:1,4,7 kw2:2,5,8)
                float4 B = *(const float4*)(g + 4);  // slots 4..7
                float  C = g[8];                     // slot 8
                float x00 = xv[a][h][0][0], x01 = xv[a][h][0][1], x02 = xv[a][h][0][2];
                float x10 = xv[a][h][1][0], x11 = xv[a][h][1][1], x12 = xv[a][h][1][2];
                float x20 = xv[a][h][2][0], x21 = xv[a][h][2][1], x22 = xv[a][h][2][2];
                // ow=4c: kw1 @ j0
                v0 = fmaf(A.y, x00, v0); v0 = fmaf(B.x, x10, v0); v0 = fmaf(B.w, x20, v0);
                // ow=4c+2: kw1 @ j1
                v2 = fmaf(A.y, x01, v2); v2 = fmaf(B.x, x11, v2); v2 = fmaf(B.w, x21, v2);
                // ow=4c+1: kw0 @ j1, kw2 @ j0
                v1 = fmaf(A.x, x01, v1); v1 = fmaf(A.w, x11, v1); v1 = fmaf(B.z, x21, v1);
                v1 = fmaf(A.z, x00, v1); v1 = fmaf(B.y, x10, v1); v1 = fmaf(C,   x20, v1);
                // ow=4c+3: kw0 @ j2, kw2 @ j1
                v3 = fmaf(A.x, x02, v3); v3 = fmaf(A.w, x12, v3); v3 = fmaf(B.z, x22, v3);
                v3 = fmaf(A.z, x01, v3); v3 = fmaf(B.y, x11, v3); v3 = fmaf(C,   x21, v3);
            }
        }
        s0 += __expf(v0); s1 += __expf(v1); s2 += __expf(v2); s3 += __expf(v3);
    }

    float l0 = __logf(s0), l1 = __logf(s1), l2 = __logf(s2), l3 = __logf(s3);
    float h0 = __fdividef(l0, 6.f * (1.f + __expf(-(l0 + 3.f))));
    float h1 = __fdividef(l1, 6.f * (1.f + __expf(-(l1 + 3.f))));
    float h2 = __fdividef(l2, 6.f * (1.f + __expf(-(l2 + 3.f))));
    float h3 = __fdividef(l3, 6.f * (1.f + __expf(-(l3 + 3.f))));
    int wb = 4 * c;
    op[wb]     = fminf(fmaxf(h0 - bv, -1.f), 1.f);
    op[wb + 1] = fminf(fmaxf(h1 - bv, -1.f), 1.f);
    op[wb + 2] = fminf(fmaxf(h2 - bv, -1.f), 1.f);
    if (wb + 3 < 63) op[wb + 3] = fminf(fmaxf(h3 - bv, -1.f), 1.f);
}

__global__ __launch_bounds__(256)
void fused_convT_lse_hs_v5(
    const float* __restrict__ x,
    const float* __restrict__ w,
    const float* __restrict__ bias,
    float* __restrict__ out)
{
    __shared__ __align__(16) float sw[WSH];
    // src w[ic*432 + oc*27 + kd*9 + kh*3 + kw]
    for (int i = threadIdx.x; i < 1296; i += 256) {
        int ic = i / 432;  int r = i - ic * 432;
        int oc = r / 27;   int tap = r - oc * 27;
        int kd = tap / 9;  int t2 = tap - kd * 9;
        int kh = t2 / 3;   int kw = t2 - kh * 3;
        sw[((oc * 3 + kd) * 3 + kh) * 12 + ic * 3 + kw] = w[i];
    }
    __syncthreads();

    int warp = threadIdx.x >> 5;
    int lane = threadIdx.x & 31;
    int half = lane >> 4;          // 2 rows per warp (same parity class)
    int c    = lane & 15;          // lane's ow group: 4c..4c+3

    int gw = blockIdx.x * 8 + warp;   // global warp id, class-concatenated
    // Class warp counts: 8192 / 7936 / 7680 / 7440 (all %8==0), total 31248.
    int cls, r;
    if (gw < 8192)       { cls = 0; r = 2 * gw + half; }
    else if (gw < 16128) { cls = 1; r = 2 * (gw - 8192) + half; }
    else if (gw < 23808) { cls = 2; r = 2 * (gw - 16128) + half; }
    else                 { cls = 3; r = 2 * (gw - 23808) + half; }

    int pd = cls >> 1, ph = cls & 1;
    int nhc = ph ? 31 : 32;
    int per_b = (pd ? 15 : 16) * nhc;
    int b = r / per_b; int rem = r - b * per_b;
    int idd = rem / nhc; int ihh = rem - idd * nhc;
    int od = 2 * idd + pd, oh = 2 * ihh + ph;

    const float* xb = x + (size_t)b * XB;
    float* op = out + ((size_t)(b * 31 + od) * 63 + oh) * 63;
    float bv = __ldg(bias);

    int id0, id1 = 0, ih0, ih1 = 0;
    if (pd) { id0 = (od + 1) >> 1; id1 = (od - 1) >> 1; } else id0 = od >> 1;
    if (ph) { ih0 = (oh + 1) >> 1; ih1 = (oh - 1) >> 1; } else ih0 = oh >> 1;

    if (cls == 0)      run_quad<1, 1>(xb, sw, op, id0, id1, ih0, ih1, c, bv);
    else if (cls == 1) run_quad<1, 2>(xb, sw, op, id0, id1, ih0, ih1, c, bv);
    else if (cls == 2) run_quad<2, 1>(xb, sw, op, id0, id1, ih0, ih1, c, bv);
    else               run_quad<2, 2>(xb, sw, op, id0, id1, ih0, ih1, c, bv);
}

extern "C" void kernel_launch(void* const* d_in, const int* in_sizes, int n_in,
                              void* d_out, int out_size)
{
    const float* x    = (const float*)d_in[0];
    const float* w    = (const float*)d_in[1];
    const float* bias = (const float*)d_in[2];
    float* out        = (float*)d_out;
    // 31248 warps, 8 per block -> 3906 blocks
    fused_convT_lse_hs_v5<<<3906, 256>>>(x, w, bias, out);
}